// round 1
// baseline (speedup 1.0000x reference)
#include <cuda_runtime.h>

// WaterNetModel scan: NT=1096 timesteps, NS=2048 sites, NH=16 buckets.
// One thread per (site, bucket). State (s, h) carried in registers across the
// time loop. Q reduced over the 16-lane bucket group via shfl butterfly.
// Outputs concatenated in d_out: Q [NT,NS] | H [NT,NS,NH] | S [NT,NS,NH].

#define NT 1096
#define NS 2048
#define NH 16
#define PF 8   // prefetch depth (NT % PF == 0)

__global__ __launch_bounds__(64, 16)
void waternet_kernel(const float* __restrict__ P,
                     const float* __restrict__ T,
                     const float* __restrict__ w_i,
                     const float* __restrict__ w_o,
                     const float* __restrict__ w_l,
                     const float* __restrict__ w_s,
                     float* __restrict__ Q,
                     float* __restrict__ H,
                     float* __restrict__ S)
{
    const int g    = blockIdx.x * blockDim.x + threadIdx.x;  // 0..32767
    const int h    = g & (NH - 1);
    const int site = g >> 4;

    // ---- time-invariant gate factors (cheap, once per thread) ----
    const float melt = expf(w_s[h]) + 1.0f;
    const float gi   = 1.0f / (1.0f + expf(-w_i[h]));
    const float gl   = 1.0f / (1.0f + expf(-w_l[h]));

    // softmax over w_o (NH=16, redundant per thread, trivial)
    float mx = w_o[0];
    #pragma unroll
    for (int j = 1; j < NH; j++) mx = fmaxf(mx, w_o[j]);
    float ssum = 0.0f;
    #pragma unroll
    for (int j = 0; j < NH; j++) ssum += expf(w_o[j] - mx);
    const float a = expf(w_o[h] - mx) / ssum;

    // ---- state ----
    float s  = 0.0f;
    float hh = 0.0f;

    const float* Pp = P + site;
    const float* Tp = T + site;

    // register prefetch pipeline
    float pb[PF], tb[PF];
    #pragma unroll
    for (int i = 0; i < PF; i++) {
        pb[i] = __ldg(Pp + i * NS);
        tb[i] = __ldg(Tp + i * NS);
    }

    for (int t0 = 0; t0 < NT; t0 += PF) {
        #pragma unroll
        for (int k = 0; k < PF; k++) {
            const int t = t0 + k;
            const float Pk = pb[k];
            const float Tk = tb[k];

            // prefetch PF steps ahead
            const int tn = t + PF;
            if (tn < NT) {
                pb[k] = __ldg(Pp + tn * NS);
                tb[k] = __ldg(Tp + tn * NS);
            }

            // SnowBucket
            const float sm = fmaxf(Tk, 0.0f) * melt;
            const float m  = fminf(sm, s);
            const float sn = s - m + ((Tk < 0.0f) ? Pk : 0.0f);
            const float x  = ((Tk > 0.0f) ? Pk : 0.0f) + m;

            // input gate + LinearBucket
            const float xin = x * gi;
            const float u   = xin + hh;   // (h + xin)
            const float q   = u * gl;
            const float hn  = u - q;      // h - q + xin

            s  = sn;
            hh = hn;

            // coalesced state stores
            const int o = t * (NS * NH) + g;
            H[o] = hn;
            S[o] = sn;

            // Q = sum_h q*a over the 16-lane bucket group
            float qa = q * a;
            qa += __shfl_xor_sync(0xFFFFFFFFu, qa, 1);
            qa += __shfl_xor_sync(0xFFFFFFFFu, qa, 2);
            qa += __shfl_xor_sync(0xFFFFFFFFu, qa, 4);
            qa += __shfl_xor_sync(0xFFFFFFFFu, qa, 8);
            if (h == 0) Q[t * NS + site] = qa;
        }
    }
}

extern "C" void kernel_launch(void* const* d_in, const int* in_sizes, int n_in,
                              void* d_out, int out_size)
{
    const float* P   = (const float*)d_in[0];
    const float* T   = (const float*)d_in[1];
    const float* w_i = (const float*)d_in[2];
    const float* w_o = (const float*)d_in[3];
    const float* w_l = (const float*)d_in[4];
    const float* w_s = (const float*)d_in[5];

    float* Q = (float*)d_out;                    // NT*NS
    float* H = Q + (size_t)NT * NS;              // NT*NS*NH
    float* S = H + (size_t)NT * NS * NH;         // NT*NS*NH

    const int threads = 64;
    const int blocks  = (NS * NH) / threads;     // 512
    waternet_kernel<<<blocks, threads>>>(P, T, w_i, w_o, w_l, w_s, Q, H, S);
}